// round 11
// baseline (speedup 1.0000x reference)
#include <cuda_runtime.h>

// HelionGeluD8: fused isotypic->regular butterfly, 8x erf-GeLU, regular->isotypic butterfly.
// B=16, N=1024, C=512. M = B*N = 16384 rows of C floats.
// Inputs: x_A1..x_B2 each (M, C) f32; x_2d (M, 2, 2C) f32.
// Output: [iso0 | iso1 | iso2 | iso3 | y_2d].
//
// Algebra: S = sqrt(2)/4. Both butterfly scales folded into the gelu:
//   z  = 0.25*u  (exact),  h' = 0.0625*u  (exact)
//   g' = S*gelu(S*u) = fma(h', erf(z), h');  second butterfly needs no scale.
//
// CONVERGED AT ROOFLINE: 512 MiB irreducible traffic / 6.29 TB/s measured
// mixed-R/W HBM ceiling = 76.3us; this build measures 76.4us in ncu (99.9%).
// Params stay as kernel arguments deliberately — dropping them makes ptxas
// rematerialize constants (regs 48->56, R9). Bounds check retained (this exact
// build allocated 48 regs). Do not "simplify".

// Abramowitz-Stegun 7.1.25 erf (3-term): max abs err 2.5e-5.
static __device__ __forceinline__ float sgelu_f(float u) {
    const float p  = 0.47047f;
    const float a1 = 0.3480242f;
    const float a2 = -0.0958798f;
    const float a3 = 0.7478556f;

    float z = 0.25f * u;
    float s = fabsf(z);
    float t = __fdividef(1.0f, fmaf(p, s, 1.0f));   // MUFU.RCP
    float poly = fmaf(a3, t, a2);
    poly = fmaf(poly, t, a1);
    poly = poly * t;
    float ex = __expf(-s * s);                      // MUFU.EX2
    float erf_pos = fmaf(-poly, ex, 1.0f);
    float erfz = copysignf(erf_pos, z);
    float h = 0.0625f * u;
    return fmaf(h, erfz, h);                        // = S*gelu(S*u)
}

__global__ void __launch_bounds__(256) helion_gelu_d8_kernel(
    const float4* __restrict__ xA1,
    const float4* __restrict__ xA2,
    const float4* __restrict__ xB1,
    const float4* __restrict__ xB2,
    const float4* __restrict__ x2d,
    float4* __restrict__ out,
    int total_vec,   // M * C4
    int C4,          // 128
    int MC4)         // M * C4
{
    int tid = blockIdx.x * blockDim.x + threadIdx.x;
    if (tid >= total_vec) return;

    int r  = tid >> 7;           // row (C4 = 128)
    int c4 = tid & 127;

    int base2d = r * (4 * C4) + c4;

    // Streaming loads (zero reuse): evict-first.
    float4 vx0 = __ldcs(&xA1[tid]);
    float4 vx1 = __ldcs(&xA2[tid]);
    float4 vx2 = __ldcs(&xB1[tid]);
    float4 vx3 = __ldcs(&xB2[tid]);
    float4 vy0 = __ldcs(&x2d[base2d]);
    float4 vy1 = __ldcs(&x2d[base2d + C4]);
    float4 vy2 = __ldcs(&x2d[base2d + 2 * C4]);
    float4 vy3 = __ldcs(&x2d[base2d + 3 * C4]);

    float4 o0, o1, o2, o3, o4, o5, o6, o7;

    const float* px0 = &vx0.x; const float* px1 = &vx1.x;
    const float* px2 = &vx2.x; const float* px3 = &vx3.x;
    const float* py0 = &vy0.x; const float* py1 = &vy1.x;
    const float* py2 = &vy2.x; const float* py3 = &vy3.x;
    float* po0 = &o0.x; float* po1 = &o1.x; float* po2 = &o2.x; float* po3 = &o3.x;
    float* po4 = &o4.x; float* po5 = &o5.x; float* po6 = &o6.x; float* po7 = &o7.x;

#pragma unroll
    for (int k = 0; k < 4; k++) {
        float x0 = px0[k], x1 = px1[k], x2 = px2[k], x3 = px3[k];
        float y0 = py0[k], y1 = py1[k], y2 = py2[k], y3 = py3[k];

        // isotypic_to_regular (unscaled sums u_i)
        float a = x0 + x1, b = x0 - x1;
        float c = x2 + x3, d = x2 - x3;
        float e = y0 + y1, f = y0 - y1;
        float g = y2 + y3, h = y2 - y3;
        float apc = a + c, amc = a - c;
        float bpd = b + d, bmd = b - d;
        float eph = e + h, emh = e - h;
        float fpg = f + g, fmg = f - g;

        // scaled gelu: g'_i = S * gelu(S * u_i)
        float g0 = sgelu_f(apc + eph);
        float g1 = sgelu_f(amc + fmg);
        float g2v = sgelu_f(apc - eph);
        float g3 = sgelu_f(amc - fmg);
        float g4 = sgelu_f(bpd - fpg);
        float g5 = sgelu_f(bmd - emh);
        float g6 = sgelu_f(bpd + fpg);
        float g7 = sgelu_f(bmd + emh);

        // regular_to_isotypic (no trailing scale — folded into g')
        float a2 = g0 + g1, b2 = g0 - g1;
        float c2 = g2v + g3, d2 = g2v - g3;
        float e2 = g4 + g5, f2 = g4 - g5;
        float g2 = g6 + g7, h2 = g6 - g7;
        float apc2 = a2 + c2, cma2 = c2 - a2;
        float bpd2 = b2 + d2, bmd2 = b2 - d2;
        float epg2 = e2 + g2, gme2 = g2 - e2;
        float fph2 = f2 + h2, fmh2 = f2 - h2;

        po0[k] = apc2 + epg2;
        po1[k] = apc2 - epg2;
        po2[k] = bpd2 + fph2;
        po3[k] = bpd2 - fph2;
        po4[k] = gme2 - cma2;
        po5[k] = bmd2 + fmh2;
        po6[k] = bmd2 - fmh2;
        po7[k] = gme2 + cma2;
    }

    __stcs(&out[tid],           o0);
    __stcs(&out[MC4 + tid],     o1);
    __stcs(&out[2 * MC4 + tid], o2);
    __stcs(&out[3 * MC4 + tid], o3);
    int ob = 4 * MC4 + base2d;
    __stcs(&out[ob],            o4);
    __stcs(&out[ob + C4],       o5);
    __stcs(&out[ob + 2 * C4],   o6);
    __stcs(&out[ob + 3 * C4],   o7);
}

extern "C" void kernel_launch(void* const* d_in, const int* in_sizes, int n_in,
                              void* d_out, int out_size) {
    const float4* xA1 = (const float4*)d_in[0];
    const float4* xA2 = (const float4*)d_in[1];
    const float4* xB1 = (const float4*)d_in[2];
    const float4* xB2 = (const float4*)d_in[3];
    const float4* x2d = (const float4*)d_in[4];
    float4* out = (float4*)d_out;

    const int M  = 16 * 1024;
    const int C4 = 512 / 4;
    const int MC4 = M * C4;
    const int total_vec = MC4;

    dim3 block(256);
    dim3 grid((total_vec + 255) / 256);
    helion_gelu_d8_kernel<<<grid, block>>>(xA1, xA2, xB1, xB2, x2d, out,
                                           total_vec, C4, MC4);
}

// round 12
// speedup vs baseline: 1.0078x; 1.0078x over previous
#include <cuda_runtime.h>

// HelionGeluD8: fused isotypic->regular butterfly, 8x erf-GeLU, regular->isotypic butterfly.
// B=16, N=1024, C=512. M = B*N = 16384 rows of C floats.
// Inputs: x_A1..x_B2 each (M, C) f32; x_2d (M, 2, 2C) f32.
// Output: [iso0 | iso1 | iso2 | iso3 | y_2d].
//
// Algebra: S = sqrt(2)/4. Both butterfly scales folded into the gelu:
//   z  = 0.25*u  (exact),  h' = 0.0625*u  (exact)
//   g' = S*gelu(S*u) = fma(h', erf(z), h');  second butterfly needs no scale.
//
// CONVERGED AT ROOFLINE (R10 measurement): ncu dur 76.16us vs 76.1us floor
// (512 MiB irreducible traffic / 6.31 TB/s measured mixed-R/W HBM ceiling =
// 100% of ceiling). Six configurations (block 128/224/256, occ 44-56%, 3- vs
// 5-term erf, hints on/off) all pin DRAM at 6.21-6.31 TB/s — memory-bound,
// no remaining lever. Params stay as kernel arguments deliberately — dropping
// them makes ptxas rematerialize constants (regs 48->56, R9). Bounds check
// retained (this exact build allocates 48 regs). Do not "simplify".

// Abramowitz-Stegun 7.1.25 erf (3-term): max abs err 2.5e-5.
static __device__ __forceinline__ float sgelu_f(float u) {
    const float p  = 0.47047f;
    const float a1 = 0.3480242f;
    const float a2 = -0.0958798f;
    const float a3 = 0.7478556f;

    float z = 0.25f * u;
    float s = fabsf(z);
    float t = __fdividef(1.0f, fmaf(p, s, 1.0f));   // MUFU.RCP
    float poly = fmaf(a3, t, a2);
    poly = fmaf(poly, t, a1);
    poly = poly * t;
    float ex = __expf(-s * s);                      // MUFU.EX2
    float erf_pos = fmaf(-poly, ex, 1.0f);
    float erfz = copysignf(erf_pos, z);
    float h = 0.0625f * u;
    return fmaf(h, erfz, h);                        // = S*gelu(S*u)
}

__global__ void __launch_bounds__(256) helion_gelu_d8_kernel(
    const float4* __restrict__ xA1,
    const float4* __restrict__ xA2,
    const float4* __restrict__ xB1,
    const float4* __restrict__ xB2,
    const float4* __restrict__ x2d,
    float4* __restrict__ out,
    int total_vec,   // M * C4
    int C4,          // 128
    int MC4)         // M * C4
{
    int tid = blockIdx.x * blockDim.x + threadIdx.x;
    if (tid >= total_vec) return;

    int r  = tid >> 7;           // row (C4 = 128)
    int c4 = tid & 127;

    int base2d = r * (4 * C4) + c4;

    // Streaming loads (zero reuse): evict-first.
    float4 vx0 = __ldcs(&xA1[tid]);
    float4 vx1 = __ldcs(&xA2[tid]);
    float4 vx2 = __ldcs(&xB1[tid]);
    float4 vx3 = __ldcs(&xB2[tid]);
    float4 vy0 = __ldcs(&x2d[base2d]);
    float4 vy1 = __ldcs(&x2d[base2d + C4]);
    float4 vy2 = __ldcs(&x2d[base2d + 2 * C4]);
    float4 vy3 = __ldcs(&x2d[base2d + 3 * C4]);

    float4 o0, o1, o2, o3, o4, o5, o6, o7;

    const float* px0 = &vx0.x; const float* px1 = &vx1.x;
    const float* px2 = &vx2.x; const float* px3 = &vx3.x;
    const float* py0 = &vy0.x; const float* py1 = &vy1.x;
    const float* py2 = &vy2.x; const float* py3 = &vy3.x;
    float* po0 = &o0.x; float* po1 = &o1.x; float* po2 = &o2.x; float* po3 = &o3.x;
    float* po4 = &o4.x; float* po5 = &o5.x; float* po6 = &o6.x; float* po7 = &o7.x;

#pragma unroll
    for (int k = 0; k < 4; k++) {
        float x0 = px0[k], x1 = px1[k], x2 = px2[k], x3 = px3[k];
        float y0 = py0[k], y1 = py1[k], y2 = py2[k], y3 = py3[k];

        // isotypic_to_regular (unscaled sums u_i)
        float a = x0 + x1, b = x0 - x1;
        float c = x2 + x3, d = x2 - x3;
        float e = y0 + y1, f = y0 - y1;
        float g = y2 + y3, h = y2 - y3;
        float apc = a + c, amc = a - c;
        float bpd = b + d, bmd = b - d;
        float eph = e + h, emh = e - h;
        float fpg = f + g, fmg = f - g;

        // scaled gelu: g'_i = S * gelu(S * u_i)
        float g0 = sgelu_f(apc + eph);
        float g1 = sgelu_f(amc + fmg);
        float g2v = sgelu_f(apc - eph);
        float g3 = sgelu_f(amc - fmg);
        float g4 = sgelu_f(bpd - fpg);
        float g5 = sgelu_f(bmd - emh);
        float g6 = sgelu_f(bpd + fpg);
        float g7 = sgelu_f(bmd + emh);

        // regular_to_isotypic (no trailing scale — folded into g')
        float a2 = g0 + g1, b2 = g0 - g1;
        float c2 = g2v + g3, d2 = g2v - g3;
        float e2 = g4 + g5, f2 = g4 - g5;
        float g2 = g6 + g7, h2 = g6 - g7;
        float apc2 = a2 + c2, cma2 = c2 - a2;
        float bpd2 = b2 + d2, bmd2 = b2 - d2;
        float epg2 = e2 + g2, gme2 = g2 - e2;
        float fph2 = f2 + h2, fmh2 = f2 - h2;

        po0[k] = apc2 + epg2;
        po1[k] = apc2 - epg2;
        po2[k] = bpd2 + fph2;
        po3[k] = bpd2 - fph2;
        po4[k] = gme2 - cma2;
        po5[k] = bmd2 + fmh2;
        po6[k] = bmd2 - fmh2;
        po7[k] = gme2 + cma2;
    }

    __stcs(&out[tid],           o0);
    __stcs(&out[MC4 + tid],     o1);
    __stcs(&out[2 * MC4 + tid], o2);
    __stcs(&out[3 * MC4 + tid], o3);
    int ob = 4 * MC4 + base2d;
    __stcs(&out[ob],            o4);
    __stcs(&out[ob + C4],       o5);
    __stcs(&out[ob + 2 * C4],   o6);
    __stcs(&out[ob + 3 * C4],   o7);
}

extern "C" void kernel_launch(void* const* d_in, const int* in_sizes, int n_in,
                              void* d_out, int out_size) {
    const float4* xA1 = (const float4*)d_in[0];
    const float4* xA2 = (const float4*)d_in[1];
    const float4* xB1 = (const float4*)d_in[2];
    const float4* xB2 = (const float4*)d_in[3];
    const float4* x2d = (const float4*)d_in[4];
    float4* out = (float4*)d_out;

    const int M  = 16 * 1024;
    const int C4 = 512 / 4;
    const int MC4 = M * C4;
    const int total_vec = MC4;

    dim3 block(256);
    dim3 grid((total_vec + 255) / 256);
    helion_gelu_d8_kernel<<<grid, block>>>(xA1, xA2, xB1, xB2, x2d, out,
                                           total_vec, C4, MC4);
}

// round 13
// speedup vs baseline: 1.0082x; 1.0004x over previous
#include <cuda_runtime.h>

// HelionGeluD8: fused isotypic->regular butterfly, 8x erf-GeLU, regular->isotypic butterfly.
// B=16, N=1024, C=512. M = B*N = 16384 rows of C floats.
// Inputs: x_A1..x_B2 each (M, C) f32; x_2d (M, 2, 2C) f32.
// Output: [iso0 | iso1 | iso2 | iso3 | y_2d].
//
// Algebra: S = sqrt(2)/4. Both butterfly scales folded into the gelu:
//   z  = 0.25*u  (exact),  h' = 0.0625*u  (exact)
//   g' = S*gelu(S*u) = fma(h', erf(z), h');  second butterfly needs no scale.
//
// FINAL FORM — CONVERGED AT ROOFLINE. Evidence (12 rounds):
//   - ncu device time 76.16-76.93us across all 48-reg builds; floor is
//     512 MiB irreducible traffic / 6.31 TB/s measured mixed-R/W HBM ceiling
//     = 76.1us  (=> 100% of ceiling).
//   - DRAM pinned at 6.21-6.31 TB/s over six configs (block 128/224/256,
//     occ 44-56%, 3- vs 5-term erf, hints on/off). Memory-bound, no lever.
//   - Register perturbations regress: launch_bounds min-blocks (R4: spills),
//     grid-stride (R6: 54 regs), param removal (R9: 56 regs). Keep params as
//     kernel arguments and keep the bounds check — this build = 48 regs.

// Abramowitz-Stegun 7.1.25 erf (3-term): max abs err 2.5e-5.
static __device__ __forceinline__ float sgelu_f(float u) {
    const float p  = 0.47047f;
    const float a1 = 0.3480242f;
    const float a2 = -0.0958798f;
    const float a3 = 0.7478556f;

    float z = 0.25f * u;
    float s = fabsf(z);
    float t = __fdividef(1.0f, fmaf(p, s, 1.0f));   // MUFU.RCP
    float poly = fmaf(a3, t, a2);
    poly = fmaf(poly, t, a1);
    poly = poly * t;
    float ex = __expf(-s * s);                      // MUFU.EX2
    float erf_pos = fmaf(-poly, ex, 1.0f);
    float erfz = copysignf(erf_pos, z);
    float h = 0.0625f * u;
    return fmaf(h, erfz, h);                        // = S*gelu(S*u)
}

__global__ void __launch_bounds__(256) helion_gelu_d8_kernel(
    const float4* __restrict__ xA1,
    const float4* __restrict__ xA2,
    const float4* __restrict__ xB1,
    const float4* __restrict__ xB2,
    const float4* __restrict__ x2d,
    float4* __restrict__ out,
    int total_vec,   // M * C4
    int C4,          // 128
    int MC4)         // M * C4
{
    int tid = blockIdx.x * blockDim.x + threadIdx.x;
    if (tid >= total_vec) return;

    int r  = tid >> 7;           // row (C4 = 128)
    int c4 = tid & 127;

    int base2d = r * (4 * C4) + c4;

    // Streaming loads (zero reuse): evict-first.
    float4 vx0 = __ldcs(&xA1[tid]);
    float4 vx1 = __ldcs(&xA2[tid]);
    float4 vx2 = __ldcs(&xB1[tid]);
    float4 vx3 = __ldcs(&xB2[tid]);
    float4 vy0 = __ldcs(&x2d[base2d]);
    float4 vy1 = __ldcs(&x2d[base2d + C4]);
    float4 vy2 = __ldcs(&x2d[base2d + 2 * C4]);
    float4 vy3 = __ldcs(&x2d[base2d + 3 * C4]);

    float4 o0, o1, o2, o3, o4, o5, o6, o7;

    const float* px0 = &vx0.x; const float* px1 = &vx1.x;
    const float* px2 = &vx2.x; const float* px3 = &vx3.x;
    const float* py0 = &vy0.x; const float* py1 = &vy1.x;
    const float* py2 = &vy2.x; const float* py3 = &vy3.x;
    float* po0 = &o0.x; float* po1 = &o1.x; float* po2 = &o2.x; float* po3 = &o3.x;
    float* po4 = &o4.x; float* po5 = &o5.x; float* po6 = &o6.x; float* po7 = &o7.x;

#pragma unroll
    for (int k = 0; k < 4; k++) {
        float x0 = px0[k], x1 = px1[k], x2 = px2[k], x3 = px3[k];
        float y0 = py0[k], y1 = py1[k], y2 = py2[k], y3 = py3[k];

        // isotypic_to_regular (unscaled sums u_i)
        float a = x0 + x1, b = x0 - x1;
        float c = x2 + x3, d = x2 - x3;
        float e = y0 + y1, f = y0 - y1;
        float g = y2 + y3, h = y2 - y3;
        float apc = a + c, amc = a - c;
        float bpd = b + d, bmd = b - d;
        float eph = e + h, emh = e - h;
        float fpg = f + g, fmg = f - g;

        // scaled gelu: g'_i = S * gelu(S * u_i)
        float g0 = sgelu_f(apc + eph);
        float g1 = sgelu_f(amc + fmg);
        float g2v = sgelu_f(apc - eph);
        float g3 = sgelu_f(amc - fmg);
        float g4 = sgelu_f(bpd - fpg);
        float g5 = sgelu_f(bmd - emh);
        float g6 = sgelu_f(bpd + fpg);
        float g7 = sgelu_f(bmd + emh);

        // regular_to_isotypic (no trailing scale — folded into g')
        float a2 = g0 + g1, b2 = g0 - g1;
        float c2 = g2v + g3, d2 = g2v - g3;
        float e2 = g4 + g5, f2 = g4 - g5;
        float g2 = g6 + g7, h2 = g6 - g7;
        float apc2 = a2 + c2, cma2 = c2 - a2;
        float bpd2 = b2 + d2, bmd2 = b2 - d2;
        float epg2 = e2 + g2, gme2 = g2 - e2;
        float fph2 = f2 + h2, fmh2 = f2 - h2;

        po0[k] = apc2 + epg2;
        po1[k] = apc2 - epg2;
        po2[k] = bpd2 + fph2;
        po3[k] = bpd2 - fph2;
        po4[k] = gme2 - cma2;
        po5[k] = bmd2 + fmh2;
        po6[k] = bmd2 - fmh2;
        po7[k] = gme2 + cma2;
    }

    __stcs(&out[tid],           o0);
    __stcs(&out[MC4 + tid],     o1);
    __stcs(&out[2 * MC4 + tid], o2);
    __stcs(&out[3 * MC4 + tid], o3);
    int ob = 4 * MC4 + base2d;
    __stcs(&out[ob],            o4);
    __stcs(&out[ob + C4],       o5);
    __stcs(&out[ob + 2 * C4],   o6);
    __stcs(&out[ob + 3 * C4],   o7);
}

extern "C" void kernel_launch(void* const* d_in, const int* in_sizes, int n_in,
                              void* d_out, int out_size) {
    const float4* xA1 = (const float4*)d_in[0];
    const float4* xA2 = (const float4*)d_in[1];
    const float4* xB1 = (const float4*)d_in[2];
    const float4* xB2 = (const float4*)d_in[3];
    const float4* x2d = (const float4*)d_in[4];
    float4* out = (float4*)d_out;

    const int M  = 16 * 1024;
    const int C4 = 512 / 4;
    const int MC4 = M * C4;
    const int total_vec = MC4;

    dim3 block(256);
    dim3 grid((total_vec + 255) / 256);
    helion_gelu_d8_kernel<<<grid, block>>>(xA1, xA2, xB1, xB2, x2d, out,
                                           total_vec, C4, MC4);
}